// round 15
// baseline (speedup 1.0000x reference)
#include <cuda_runtime.h>
#include <math.h>
#include <stdint.h>

#define NN 50000
#define NE 800000
#define FIN 128
#define D1 256
#define D2 128
#define KC 32

// ---------------- scratch (device globals; zero-init at load, re-zeroed at end of each run) ----------------
__device__ __align__(16) float g_aggX[(size_t)NN * FIN];  // normalized (A+I) agg of features
__device__ __align__(16) float g_S[(size_t)NN * KC];      // softmax assign
__device__ __align__(16) float g_V[(size_t)NN * KC];      // S - W^T S (for adj)
__device__ __align__(16) float g_Wc[FIN * D2];            // W1 @ fc1W  (128x128) [k][n]
__device__ float g_bc[D2];                                 // b1 @ fc1W + fc1b
__device__ __align__(16) int g_deg[2 * NN];                // [0,NN): deg_in  [NN,2NN): deg_out  (zeroed by k_adj)
__device__ int   g_off_in[NN + 1];                         // exclusive offsets; post-fill = segment ENDs
__device__ int   g_src_in[NE];                             // CSR by target: source ids
__device__ float g_dinv1[NN], g_dinv2[NN];
__device__ __align__(16) float g_small[KC * KC + FIN];     // [0,1024): adj  [1024,1152): cs  (zeroed by k_final)

#define G_ADJ(i) g_small[i]
#define G_CS(i)  g_small[KC * KC + (i)]

// ---------------- degree histogram (int4 edge loads) ----------------
__global__ void k_degree(const int* __restrict__ e) {
    int i = blockIdx.x * blockDim.x + threadIdx.x;
    int stride = gridDim.x * blockDim.x;
    const int4* e4r = (const int4*)e;
    const int4* e4c = (const int4*)(e + NE);
    int n4 = NE / 4;
    for (int j = i; j < n4; j += stride) {
        int4 r = e4r[j];
        int4 c = e4c[j];
        atomicAdd(&g_deg[NN + r.x], 1);
        atomicAdd(&g_deg[NN + r.y], 1);
        atomicAdd(&g_deg[NN + r.z], 1);
        atomicAdd(&g_deg[NN + r.w], 1);
        atomicAdd(&g_deg[c.x], 1);
        atomicAdd(&g_deg[c.y], 1);
        atomicAdd(&g_deg[c.z], 1);
        atomicAdd(&g_deg[c.w], 1);
    }
}

// block 0: scan deg_in -> off_in, emit dinv1.  block 1: dinv2 from deg_out.
__global__ __launch_bounds__(1024) void k_scan2() {
    int t = threadIdx.x;
    if (blockIdx.x == 1) {
        for (int idx = t; idx < NN; idx += 1024) {
            int v = g_deg[NN + idx];
            g_dinv2[idx] = (v > 0) ? rsqrtf((float)v) : 0.f;
        }
        return;
    }
    __shared__ int wsum[32];
    __shared__ int carry;
    int lane = t & 31, w = t >> 5;
    if (t == 0) carry = 0;
    __syncthreads();
    for (int base = 0; base < NN; base += 1024) {
        int idx = base + t;
        int v = (idx < NN) ? g_deg[idx] : 0;
        if (idx < NN) g_dinv1[idx] = rsqrtf((float)(v + 1));
        int x = v;
        #pragma unroll
        for (int o = 1; o < 32; o <<= 1) {
            int y = __shfl_up_sync(0xffffffffu, x, o);
            if (lane >= o) x += y;
        }
        if (lane == 31) wsum[w] = x;
        __syncthreads();
        if (w == 0) {
            int s = wsum[lane];
            #pragma unroll
            for (int o = 1; o < 32; o <<= 1) {
                int y = __shfl_up_sync(0xffffffffu, s, o);
                if (lane >= o) s += y;
            }
            wsum[lane] = s;
        }
        __syncthreads();
        int incl = x + (w ? wsum[w - 1] : 0);
        if (idx < NN) g_off_in[idx] = carry + incl - v;
        int total = wsum[31];
        __syncthreads();
        if (t == 0) carry += total;
        __syncthreads();
    }
}

// fill in-CSR; off_in doubles as cursor (post-fill off_in[c] = end of segment c)
__global__ void k_fill(const int* __restrict__ e) {
    int i = blockIdx.x * blockDim.x + threadIdx.x;
    int stride = gridDim.x * blockDim.x;
    const int4* e4r = (const int4*)e;
    const int4* e4c = (const int4*)(e + NE);
    int n4 = NE / 4;
    for (int j = i; j < n4; j += stride) {
        int4 r = e4r[j];
        int4 c = e4c[j];
        int p0 = atomicAdd(&g_off_in[c.x], 1);
        int p1 = atomicAdd(&g_off_in[c.y], 1);
        int p2 = atomicAdd(&g_off_in[c.z], 1);
        int p3 = atomicAdd(&g_off_in[c.w], 1);
        g_src_in[p0] = r.x;
        g_src_in[p1] = r.y;
        g_src_in[p2] = r.z;
        g_src_in[p3] = r.w;
    }
}

// ---------------- Wc = W1 @ fc1W (blocks 0-7); bc = b1@fc1W + fc1b (block 8) ----------------
__global__ __launch_bounds__(128) void k_wcbc(
    const float* __restrict__ W1, const float* __restrict__ fc1W,
    const float* __restrict__ b1, const float* __restrict__ fc1b)
{
    int tid = threadIdx.x;
    if (blockIdx.x == 8) {
        float acc = fc1b[tid];
        for (int k = 0; k < D1; k++) acc += b1[k] * fc1W[(size_t)k * D2 + tid];
        g_bc[tid] = acc;
        return;
    }
    __shared__ float w1s[8][16];
    int f0 = blockIdx.x * 16;
    float acc[16];
    #pragma unroll
    for (int f = 0; f < 16; f++) acc[f] = 0.f;
    for (int k0 = 0; k0 < D1; k0 += 8) {
        int kk = tid >> 4, ff = tid & 15;
        w1s[kk][ff] = W1[(size_t)(f0 + ff) * D1 + k0 + kk];
        __syncthreads();
        #pragma unroll
        for (int k = 0; k < 8; k++) {
            float b = fc1W[(size_t)(k0 + k) * D2 + tid];
            #pragma unroll
            for (int f = 0; f < 16; f++) acc[f] += w1s[k][f] * b;
        }
        __syncthreads();
    }
    #pragma unroll
    for (int f = 0; f < 16; f++) g_Wc[(size_t)(f0 + f) * D2 + tid] = acc[f];
}

// ---------------- feature aggregation + fused column sum (unroll x2) ----------------
__global__ __launch_bounds__(256) void k_agg(const float* __restrict__ X) {
    __shared__ float cs[8][FIN];
    int w = threadIdx.x >> 5;
    int lane = threadIdx.x & 31;
    int i = blockIdx.x * 8 + w;
    float4 o = make_float4(0.f, 0.f, 0.f, 0.f);
    if (i < NN) {
        float di = g_dinv1[i];
        const float4* X4 = (const float4*)X;
        float4 x = X4[(size_t)i * 32 + lane];
        float4 accA = make_float4(di * x.x, di * x.y, di * x.z, di * x.w);
        float4 accB = make_float4(0.f, 0.f, 0.f, 0.f);
        int s0 = i ? g_off_in[i - 1] : 0;
        int s1 = g_off_in[i];
        int idx = s0;
        for (; idx + 2 <= s1; idx += 2) {
            int sA = g_src_in[idx];
            int sB = g_src_in[idx + 1];
            float dA = g_dinv1[sA];
            float dB = g_dinv1[sB];
            float4 xA = X4[(size_t)sA * 32 + lane];
            float4 xB = X4[(size_t)sB * 32 + lane];
            accA.x += dA * xA.x; accA.y += dA * xA.y;
            accA.z += dA * xA.z; accA.w += dA * xA.w;
            accB.x += dB * xB.x; accB.y += dB * xB.y;
            accB.z += dB * xB.z; accB.w += dB * xB.w;
        }
        if (idx < s1) {
            int sA = g_src_in[idx];
            float dA = g_dinv1[sA];
            float4 xA = X4[(size_t)sA * 32 + lane];
            accA.x += dA * xA.x; accA.y += dA * xA.y;
            accA.z += dA * xA.z; accA.w += dA * xA.w;
        }
        accA.x += accB.x; accA.y += accB.y;
        accA.z += accB.z; accA.w += accB.w;
        o = make_float4(di * accA.x, di * accA.y, di * accA.z, di * accA.w);
        ((float4*)g_aggX)[(size_t)i * 32 + lane] = o;
    }
    *(float4*)&cs[w][lane * 4] = o;
    __syncthreads();
    if (threadIdx.x < FIN) {
        float s = 0.f;
        #pragma unroll
        for (int w2 = 0; w2 < 8; w2++) s += cs[w2][threadIdx.x];
        atomicAdd(&G_CS(threadIdx.x), s);
    }
}

// ---------------- fused GEMM + tanh + fc2 + softmax (scalar FFMA) ----------------
__global__ __launch_bounds__(256) void k_gemm_fused(
    const float* __restrict__ fc2W, const float* __restrict__ fc2b)
{
    const float* __restrict__ A = g_aggX;
    const float* __restrict__ B = g_Wc;
    __shared__ __align__(16) float smem_main[8 * 64 + 8 * 128]; // As | Bs = 6 KB
    __shared__ float Ws[D2 * KC];    // 16 KB fc2 weights
    __shared__ float bs_s[KC];
    float (*As)[64]  = (float(*)[64])smem_main;
    float (*Bs)[128] = (float(*)[128])(smem_main + 8 * 64);
    int tid = threadIdx.x;
    int m0 = blockIdx.x * 64;
    int tx = tid % 16, ty = tid / 16;

    for (int j = tid; j < D2 * KC; j += 256) Ws[j] = fc2W[j];
    if (tid < KC) bs_s[tid] = fc2b[tid];

    int ar = tid >> 2, ak = (tid & 3) * 2;   // A fill: row 0..63, k pair
    int bk = tid >> 5, bn = (tid & 31) * 4;  // B fill

    float acc[4][8];
    #pragma unroll
    for (int i = 0; i < 4; i++)
        #pragma unroll
        for (int j = 0; j < 8; j++) acc[i][j] = 0.f;

    // register-pipelined mainloop
    float2 av = make_float2(0.f, 0.f);
    if (m0 + ar < NN) av = *(const float2*)&A[(size_t)(m0 + ar) * FIN + ak];
    float4 bv = *(const float4*)&B[(size_t)bk * D2 + bn];

    #pragma unroll 1
    for (int k0 = 0; k0 < FIN; k0 += 8) {
        As[ak + 0][ar] = av.x;
        As[ak + 1][ar] = av.y;
        *(float4*)&Bs[bk][bn] = bv;
        __syncthreads();
        if (k0 + 8 < FIN) {
            av = make_float2(0.f, 0.f);
            if (m0 + ar < NN) av = *(const float2*)&A[(size_t)(m0 + ar) * FIN + k0 + 8 + ak];
            bv = *(const float4*)&B[(size_t)(k0 + 8 + bk) * D2 + bn];
        }
        #pragma unroll
        for (int k = 0; k < 8; k++) {
            float4 a0 = *(const float4*)&As[k][ty * 4];
            float4 b0 = *(const float4*)&Bs[k][tx * 8];
            float4 b1 = *(const float4*)&Bs[k][tx * 8 + 4];
            float aR[4] = {a0.x, a0.y, a0.z, a0.w};
            float bR[8] = {b0.x, b0.y, b0.z, b0.w, b1.x, b1.y, b1.z, b1.w};
            #pragma unroll
            for (int i = 0; i < 4; i++)
                #pragma unroll
                for (int j = 0; j < 8; j++)
                    acc[i][j] += aR[i] * bR[j];
        }
        __syncthreads();
    }

    // bias + tanh into v
    float bloc[8];
    #pragma unroll
    for (int j = 0; j < 8; j++) bloc[j] = g_bc[tx * 8 + j];
    float v[4][8];
    #pragma unroll
    for (int i = 0; i < 4; i++)
        #pragma unroll
        for (int j = 0; j < 8; j++) v[i][j] = tanhf(acc[i][j] + bloc[j]);

    // epilogue: 8 phases of 8 rows over aliased smem
    float (*abs8)[128] = (float(*)[128])smem_main;  // 4 KB <= 6 KB
    int w = tid >> 5, lane = tid & 31;
    #pragma unroll 1
    for (int ph = 0; ph < 8; ph++) {
        if ((ty >> 1) == ph) {
            int lr = (ty & 1) * 4;
            #pragma unroll
            for (int i = 0; i < 4; i++)
                #pragma unroll
                for (int j = 0; j < 8; j++)
                    abs8[lr + i][tx * 8 + j] = v[i][j];
        }
        __syncthreads();
        int grow = m0 + ph * 8 + w;  // one row per warp
        float areg[4];
        #pragma unroll
        for (int j = 0; j < 4; j++) areg[j] = abs8[w][j * 32 + lane];
        float a2 = bs_s[lane];
        #pragma unroll
        for (int j = 0; j < 4; j++)
            #pragma unroll
            for (int d = 0; d < 32; d++) {
                float a = __shfl_sync(0xffffffffu, areg[j], d);
                a2 += a * Ws[(j * 32 + d) * KC + lane];
            }
        float m = a2;
        #pragma unroll
        for (int o = 16; o > 0; o >>= 1) m = fmaxf(m, __shfl_xor_sync(0xffffffffu, m, o));
        float e = expf(a2 - m);
        float s = e;
        #pragma unroll
        for (int o = 16; o > 0; o >>= 1) s += __shfl_xor_sync(0xffffffffu, s, o);
        if (grow < NN) g_S[(size_t)grow * KC + lane] = e / s;
        __syncthreads();
    }
}

// ---------------- V[c] = S[c] - dinv2[c]*sum_{r in in(c)} dinv2[r]*S[r]  (unroll x2) ----------------
__global__ __launch_bounds__(256) void k_lapV() {
    int tid = blockIdx.x * blockDim.x + threadIdx.x;
    int lane = tid & 31;
    int i = tid >> 5;
    if (i >= NN) return;
    float sv = g_S[(size_t)i * KC + lane];
    float di = g_dinv2[i];
    float uA = 0.f, uB = 0.f;
    int s0 = i ? g_off_in[i - 1] : 0;
    int s1 = g_off_in[i];
    int idx = s0;
    for (; idx + 2 <= s1; idx += 2) {
        int rA = g_src_in[idx];
        int rB = g_src_in[idx + 1];
        uA += g_dinv2[rA] * g_S[(size_t)rA * KC + lane];
        uB += g_dinv2[rB] * g_S[(size_t)rB * KC + lane];
    }
    if (idx < s1) {
        int rA = g_src_in[idx];
        uA += g_dinv2[rA] * g_S[(size_t)rA * KC + lane];
    }
    g_V[(size_t)i * KC + lane] = sv - di * (uA + uB);
}

// ---------------- adj[a][b] = sum_i V[i,a] * S[i,b]; also re-zero g_deg for next replay ----------------
__global__ __launch_bounds__(256) void k_adj() {
    __shared__ float sh[8][KC * KC];
    int tid = threadIdx.x, lane = tid & 31, w = tid >> 5;
    // re-zero degree counters (consumed earlier this run; needed zeroed next run)
    {
        int gt = blockIdx.x * 256 + tid;
        int stride = gridDim.x * 256;
        for (int j = gt; j < 2 * NN; j += stride) g_deg[j] = 0;
    }
    float acc[32];
    #pragma unroll
    for (int a = 0; a < 32; a++) acc[a] = 0.f;
    int gw = blockIdx.x * 8 + w, tw = gridDim.x * 8;
    for (int i = gw; i < NN; i += tw) {
        float vv = g_V[(size_t)i * 32 + lane];
        float sv = g_S[(size_t)i * 32 + lane];
        #pragma unroll
        for (int a = 0; a < 32; a++) {
            float va = __shfl_sync(0xffffffffu, vv, a);
            acc[a] += va * sv;
        }
    }
    #pragma unroll
    for (int a = 0; a < 32; a++) sh[w][a * 32 + lane] = acc[a];
    __syncthreads();
    for (int j = tid; j < KC * KC; j += blockDim.x) {
        float s = 0.f;
        #pragma unroll
        for (int w2 = 0; w2 < 8; w2++) s += sh[w2][j];
        atomicAdd(&G_ADJ(j), s);
    }
}

// ---------------- finalize: emb = (cs@W1 + NN*b1)/32 ; pos_penalty; re-zero g_small ----------------
__global__ void k_final(const float* __restrict__ W1, const float* __restrict__ b1,
                        float* __restrict__ out, int out_size) {
    int t = threadIdx.x; // 256 = D1
    float acc = (float)NN * b1[t];
    for (int f = 0; f < FIN; f++) acc += G_CS(f) * W1[(size_t)f * D1 + t];
    if (t < out_size) out[t] = acc * (1.f / 32.f);
    float pen = 0.f;
    if (t < 32) {
        float rs = 0.f;
        #pragma unroll
        for (int b = 0; b < 32; b++) rs += fabsf(G_ADJ(t * 32 + b));
        float d = G_ADJ(t * 33) / fmaxf(rs, 1e-12f);
        float contrib = (d - 1.f) * (d - 1.f) + 31.f * d * d;
        #pragma unroll
        for (int o = 16; o > 0; o >>= 1) contrib += __shfl_xor_sync(0xffffffffu, contrib, o);
        pen = contrib;
    }
    __syncthreads();
    // re-zero accumulators for next replay (after all reads)
    for (int j = t; j < KC * KC + FIN; j += 256) g_small[j] = 0.f;
    if (t == 0 && out_size > D1) out[D1] = pen * (1.f / 1024.f);
}

// ---------------- launch ----------------
extern "C" void kernel_launch(void* const* d_in, const int* in_sizes, int n_in,
                              void* d_out, int out_size) {
    const float* feat  = (const float*)d_in[0];
    const int*   edges = (const int*)d_in[1];   // (2, E) int32
    const float* W1    = (const float*)d_in[2];
    const float* b1    = (const float*)d_in[3];
    const float* fc1W  = (const float*)d_in[4];
    const float* fc1b  = (const float*)d_in[5];
    const float* fc2W  = (const float*)d_in[6];
    const float* fc2b  = (const float*)d_in[7];
    float* out = (float*)d_out;

    k_degree<<<782, 256>>>(edges);                       // 0
    k_scan2<<<2, 1024>>>();                              // 1
    k_fill<<<782, 256>>>(edges);                         // 2
    k_wcbc<<<9, 128>>>(W1, fc1W, b1, fc1b);              // 3
    k_agg<<<(NN + 7) / 8, 256>>>(feat);                  // 4
    k_gemm_fused<<<(NN + 63) / 64, 256>>>(fc2W, fc2b);   // 5  <- ncu capture target
    k_lapV<<<(NN * 32 + 255) / 256, 256>>>();            // 6
    k_adj<<<148, 256>>>();                               // 7 (+ zero g_deg)
    k_final<<<1, 256>>>(W1, b1, out, out_size);          // 8 (+ zero g_small)
}

// round 16
// speedup vs baseline: 1.0351x; 1.0351x over previous
#include <cuda_runtime.h>
#include <math.h>
#include <stdint.h>

#define NN 50000
#define NE 800000
#define FIN 128
#define D1 256
#define D2 128
#define KC 32

// fast tanh: |err| ~1e-6, safe for |x| large via clamp (e^18 finite)
__device__ __forceinline__ float fast_tanh(float x) {
    float xc = fminf(fmaxf(x, -9.f), 9.f);
    float e = __expf(2.f * xc);
    return __fdividef(e - 1.f, e + 1.f);
}

// ---------------- scratch (device globals; zero-init at load, re-zeroed at end of each run) ----------------
__device__ __align__(16) float g_aggX[(size_t)NN * FIN];  // normalized (A+I) agg of features
__device__ __align__(16) float g_S[(size_t)NN * KC];      // softmax assign
__device__ __align__(16) float g_V[(size_t)NN * KC];      // S - W^T S (for adj)
__device__ __align__(16) float g_Wc[FIN * D2];            // W1 @ fc1W  (128x128) [k][n]
__device__ float g_bc[D2];                                 // b1 @ fc1W + fc1b
__device__ __align__(16) int g_deg[2 * NN];                // [0,NN): deg_in  [NN,2NN): deg_out  (zeroed by k_adj)
__device__ int   g_off_in[NN + 1];                         // exclusive offsets; post-fill = segment ENDs
__device__ int   g_src_in[NE];                             // CSR by target: source ids
__device__ float g_dinv1[NN], g_dinv2[NN];
__device__ __align__(16) float g_small[KC * KC + FIN];     // [0,1024): adj  [1024,1152): cs  (zeroed by k_final)

#define G_ADJ(i) g_small[i]
#define G_CS(i)  g_small[KC * KC + (i)]

// ---------------- degree histogram (int4 edge loads) ----------------
__global__ void k_degree(const int* __restrict__ e) {
    int i = blockIdx.x * blockDim.x + threadIdx.x;
    int stride = gridDim.x * blockDim.x;
    const int4* e4r = (const int4*)e;
    const int4* e4c = (const int4*)(e + NE);
    int n4 = NE / 4;
    for (int j = i; j < n4; j += stride) {
        int4 r = e4r[j];
        int4 c = e4c[j];
        atomicAdd(&g_deg[NN + r.x], 1);
        atomicAdd(&g_deg[NN + r.y], 1);
        atomicAdd(&g_deg[NN + r.z], 1);
        atomicAdd(&g_deg[NN + r.w], 1);
        atomicAdd(&g_deg[c.x], 1);
        atomicAdd(&g_deg[c.y], 1);
        atomicAdd(&g_deg[c.z], 1);
        atomicAdd(&g_deg[c.w], 1);
    }
}

// block 0: scan deg_in -> off_in, emit dinv1.  block 1: dinv2 from deg_out.
__global__ __launch_bounds__(1024) void k_scan2() {
    int t = threadIdx.x;
    if (blockIdx.x == 1) {
        for (int idx = t; idx < NN; idx += 1024) {
            int v = g_deg[NN + idx];
            g_dinv2[idx] = (v > 0) ? rsqrtf((float)v) : 0.f;
        }
        return;
    }
    __shared__ int wsum[32];
    __shared__ int carry;
    int lane = t & 31, w = t >> 5;
    if (t == 0) carry = 0;
    __syncthreads();
    for (int base = 0; base < NN; base += 1024) {
        int idx = base + t;
        int v = (idx < NN) ? g_deg[idx] : 0;
        if (idx < NN) g_dinv1[idx] = rsqrtf((float)(v + 1));
        int x = v;
        #pragma unroll
        for (int o = 1; o < 32; o <<= 1) {
            int y = __shfl_up_sync(0xffffffffu, x, o);
            if (lane >= o) x += y;
        }
        if (lane == 31) wsum[w] = x;
        __syncthreads();
        if (w == 0) {
            int s = wsum[lane];
            #pragma unroll
            for (int o = 1; o < 32; o <<= 1) {
                int y = __shfl_up_sync(0xffffffffu, s, o);
                if (lane >= o) s += y;
            }
            wsum[lane] = s;
        }
        __syncthreads();
        int incl = x + (w ? wsum[w - 1] : 0);
        if (idx < NN) g_off_in[idx] = carry + incl - v;
        int total = wsum[31];
        __syncthreads();
        if (t == 0) carry += total;
        __syncthreads();
    }
}

// fill in-CSR; off_in doubles as cursor (post-fill off_in[c] = end of segment c)
__global__ void k_fill(const int* __restrict__ e) {
    int i = blockIdx.x * blockDim.x + threadIdx.x;
    int stride = gridDim.x * blockDim.x;
    const int4* e4r = (const int4*)e;
    const int4* e4c = (const int4*)(e + NE);
    int n4 = NE / 4;
    for (int j = i; j < n4; j += stride) {
        int4 r = e4r[j];
        int4 c = e4c[j];
        int p0 = atomicAdd(&g_off_in[c.x], 1);
        int p1 = atomicAdd(&g_off_in[c.y], 1);
        int p2 = atomicAdd(&g_off_in[c.z], 1);
        int p3 = atomicAdd(&g_off_in[c.w], 1);
        g_src_in[p0] = r.x;
        g_src_in[p1] = r.y;
        g_src_in[p2] = r.z;
        g_src_in[p3] = r.w;
    }
}

// ---------------- feature aggregation + fused column sum (unroll x2) ----------------
__global__ __launch_bounds__(256) void k_agg(const float* __restrict__ X) {
    __shared__ float cs[8][FIN];
    int w = threadIdx.x >> 5;
    int lane = threadIdx.x & 31;
    int i = blockIdx.x * 8 + w;
    float4 o = make_float4(0.f, 0.f, 0.f, 0.f);
    if (i < NN) {
        float di = g_dinv1[i];
        const float4* X4 = (const float4*)X;
        float4 x = X4[(size_t)i * 32 + lane];
        float4 accA = make_float4(di * x.x, di * x.y, di * x.z, di * x.w);
        float4 accB = make_float4(0.f, 0.f, 0.f, 0.f);
        int s0 = i ? g_off_in[i - 1] : 0;
        int s1 = g_off_in[i];
        int idx = s0;
        for (; idx + 2 <= s1; idx += 2) {
            int sA = g_src_in[idx];
            int sB = g_src_in[idx + 1];
            float dA = g_dinv1[sA];
            float dB = g_dinv1[sB];
            float4 xA = X4[(size_t)sA * 32 + lane];
            float4 xB = X4[(size_t)sB * 32 + lane];
            accA.x += dA * xA.x; accA.y += dA * xA.y;
            accA.z += dA * xA.z; accA.w += dA * xA.w;
            accB.x += dB * xB.x; accB.y += dB * xB.y;
            accB.z += dB * xB.z; accB.w += dB * xB.w;
        }
        if (idx < s1) {
            int sA = g_src_in[idx];
            float dA = g_dinv1[sA];
            float4 xA = X4[(size_t)sA * 32 + lane];
            accA.x += dA * xA.x; accA.y += dA * xA.y;
            accA.z += dA * xA.z; accA.w += dA * xA.w;
        }
        accA.x += accB.x; accA.y += accB.y;
        accA.z += accB.z; accA.w += accB.w;
        o = make_float4(di * accA.x, di * accA.y, di * accA.z, di * accA.w);
        ((float4*)g_aggX)[(size_t)i * 32 + lane] = o;
    }
    *(float4*)&cs[w][lane * 4] = o;
    __syncthreads();
    if (threadIdx.x < FIN) {
        float s = 0.f;
        #pragma unroll
        for (int w2 = 0; w2 < 8; w2++) s += cs[w2][threadIdx.x];
        atomicAdd(&G_CS(threadIdx.x), s);
    }
}

// ---------------- Wc = W1 @ fc1W (one block per f-row; block 128 does bc) ----------------
__global__ __launch_bounds__(128) void k_wcbc(
    const float* __restrict__ W1, const float* __restrict__ fc1W,
    const float* __restrict__ b1, const float* __restrict__ fc1b)
{
    int n = threadIdx.x;   // output column 0..127
    int f = blockIdx.x;
    if (f == FIN) {
        // bc = b1 @ fc1W + fc1b
        float acc = fc1b[n];
        #pragma unroll 4
        for (int k = 0; k < D1; k++) acc += b1[k] * fc1W[(size_t)k * D2 + n];
        g_bc[n] = acc;
        return;
    }
    const float* w1row = &W1[(size_t)f * D1];
    float a0 = 0.f, a1 = 0.f, a2 = 0.f, a3 = 0.f;
    #pragma unroll 4
    for (int k = 0; k < D1; k += 4) {
        a0 += w1row[k + 0] * fc1W[(size_t)(k + 0) * D2 + n];
        a1 += w1row[k + 1] * fc1W[(size_t)(k + 1) * D2 + n];
        a2 += w1row[k + 2] * fc1W[(size_t)(k + 2) * D2 + n];
        a3 += w1row[k + 3] * fc1W[(size_t)(k + 3) * D2 + n];
    }
    g_Wc[(size_t)f * D2 + n] = (a0 + a1) + (a2 + a3);
}

// ---------------- fused GEMM + fast-tanh + fc2 + softmax ----------------
__global__ __launch_bounds__(256) void k_gemm_fused(
    const float* __restrict__ fc2W, const float* __restrict__ fc2b)
{
    const float* __restrict__ A = g_aggX;
    const float* __restrict__ B = g_Wc;
    __shared__ __align__(16) float smem_main[8 * 64 + 8 * 128]; // As | Bs = 6 KB
    __shared__ float Ws[D2 * KC];    // 16 KB fc2 weights
    __shared__ float bs_s[KC];
    float (*As)[64]  = (float(*)[64])smem_main;
    float (*Bs)[128] = (float(*)[128])(smem_main + 8 * 64);
    int tid = threadIdx.x;
    int m0 = blockIdx.x * 64;
    int tx = tid % 16, ty = tid / 16;

    for (int j = tid; j < D2 * KC; j += 256) Ws[j] = fc2W[j];
    if (tid < KC) bs_s[tid] = fc2b[tid];

    int ar = tid >> 2, ak = (tid & 3) * 2;   // A fill: row 0..63, k pair
    int bk = tid >> 5, bn = (tid & 31) * 4;  // B fill

    float acc[4][8];
    #pragma unroll
    for (int i = 0; i < 4; i++)
        #pragma unroll
        for (int j = 0; j < 8; j++) acc[i][j] = 0.f;

    // register-pipelined mainloop
    float2 av = make_float2(0.f, 0.f);
    if (m0 + ar < NN) av = *(const float2*)&A[(size_t)(m0 + ar) * FIN + ak];
    float4 bv = *(const float4*)&B[(size_t)bk * D2 + bn];

    #pragma unroll 1
    for (int k0 = 0; k0 < FIN; k0 += 8) {
        As[ak + 0][ar] = av.x;
        As[ak + 1][ar] = av.y;
        *(float4*)&Bs[bk][bn] = bv;
        __syncthreads();
        if (k0 + 8 < FIN) {
            av = make_float2(0.f, 0.f);
            if (m0 + ar < NN) av = *(const float2*)&A[(size_t)(m0 + ar) * FIN + k0 + 8 + ak];
            bv = *(const float4*)&B[(size_t)(k0 + 8 + bk) * D2 + bn];
        }
        #pragma unroll
        for (int k = 0; k < 8; k++) {
            float4 a0 = *(const float4*)&As[k][ty * 4];
            float4 b0 = *(const float4*)&Bs[k][tx * 8];
            float4 b1 = *(const float4*)&Bs[k][tx * 8 + 4];
            float aR[4] = {a0.x, a0.y, a0.z, a0.w};
            float bR[8] = {b0.x, b0.y, b0.z, b0.w, b1.x, b1.y, b1.z, b1.w};
            #pragma unroll
            for (int i = 0; i < 4; i++)
                #pragma unroll
                for (int j = 0; j < 8; j++)
                    acc[i][j] += aR[i] * bR[j];
        }
        __syncthreads();
    }

    // bias + fast tanh into v
    float bloc[8];
    #pragma unroll
    for (int j = 0; j < 8; j++) bloc[j] = g_bc[tx * 8 + j];
    float v[4][8];
    #pragma unroll
    for (int i = 0; i < 4; i++)
        #pragma unroll
        for (int j = 0; j < 8; j++) v[i][j] = fast_tanh(acc[i][j] + bloc[j]);

    // epilogue: 8 phases of 8 rows over aliased smem
    float (*abs8)[128] = (float(*)[128])smem_main;  // 4 KB <= 6 KB
    int w = tid >> 5, lane = tid & 31;
    #pragma unroll 1
    for (int ph = 0; ph < 8; ph++) {
        if ((ty >> 1) == ph) {
            int lr = (ty & 1) * 4;
            #pragma unroll
            for (int i = 0; i < 4; i++)
                #pragma unroll
                for (int j = 0; j < 8; j++)
                    abs8[lr + i][tx * 8 + j] = v[i][j];
        }
        __syncthreads();
        int grow = m0 + ph * 8 + w;  // one row per warp
        float areg[4];
        #pragma unroll
        for (int j = 0; j < 4; j++) areg[j] = abs8[w][j * 32 + lane];
        float a2 = bs_s[lane];
        #pragma unroll
        for (int j = 0; j < 4; j++)
            #pragma unroll
            for (int d = 0; d < 32; d++) {
                float a = __shfl_sync(0xffffffffu, areg[j], d);
                a2 += a * Ws[(j * 32 + d) * KC + lane];
            }
        float m = a2;
        #pragma unroll
        for (int o = 16; o > 0; o >>= 1) m = fmaxf(m, __shfl_xor_sync(0xffffffffu, m, o));
        float e = __expf(a2 - m);
        float s = e;
        #pragma unroll
        for (int o = 16; o > 0; o >>= 1) s += __shfl_xor_sync(0xffffffffu, s, o);
        if (grow < NN) g_S[(size_t)grow * KC + lane] = __fdividef(e, s);
        __syncthreads();
    }
}

// ---------------- V[c] = S[c] - dinv2[c]*sum_{r in in(c)} dinv2[r]*S[r]  (unroll x2) ----------------
__global__ __launch_bounds__(256) void k_lapV() {
    int tid = blockIdx.x * blockDim.x + threadIdx.x;
    int lane = tid & 31;
    int i = tid >> 5;
    if (i >= NN) return;
    float sv = g_S[(size_t)i * KC + lane];
    float di = g_dinv2[i];
    float uA = 0.f, uB = 0.f;
    int s0 = i ? g_off_in[i - 1] : 0;
    int s1 = g_off_in[i];
    int idx = s0;
    for (; idx + 2 <= s1; idx += 2) {
        int rA = g_src_in[idx];
        int rB = g_src_in[idx + 1];
        uA += g_dinv2[rA] * g_S[(size_t)rA * KC + lane];
        uB += g_dinv2[rB] * g_S[(size_t)rB * KC + lane];
    }
    if (idx < s1) {
        int rA = g_src_in[idx];
        uA += g_dinv2[rA] * g_S[(size_t)rA * KC + lane];
    }
    g_V[(size_t)i * KC + lane] = sv - di * (uA + uB);
}

// ---------------- adj[a][b] = sum_i V[i,a] * S[i,b]; also re-zero g_deg for next replay ----------------
__global__ __launch_bounds__(256) void k_adj() {
    __shared__ float sh[8][KC * KC];
    int tid = threadIdx.x, lane = tid & 31, w = tid >> 5;
    {
        int gt = blockIdx.x * 256 + tid;
        int stride = gridDim.x * 256;
        for (int j = gt; j < 2 * NN; j += stride) g_deg[j] = 0;
    }
    float acc[32];
    #pragma unroll
    for (int a = 0; a < 32; a++) acc[a] = 0.f;
    int gw = blockIdx.x * 8 + w, tw = gridDim.x * 8;
    for (int i = gw; i < NN; i += tw) {
        float vv = g_V[(size_t)i * 32 + lane];
        float sv = g_S[(size_t)i * 32 + lane];
        #pragma unroll
        for (int a = 0; a < 32; a++) {
            float va = __shfl_sync(0xffffffffu, vv, a);
            acc[a] += va * sv;
        }
    }
    #pragma unroll
    for (int a = 0; a < 32; a++) sh[w][a * 32 + lane] = acc[a];
    __syncthreads();
    for (int j = tid; j < KC * KC; j += blockDim.x) {
        float s = 0.f;
        #pragma unroll
        for (int w2 = 0; w2 < 8; w2++) s += sh[w2][j];
        atomicAdd(&G_ADJ(j), s);
    }
}

// ---------------- finalize: emb = (cs@W1 + NN*b1)/32 ; pos_penalty; re-zero g_small ----------------
__global__ void k_final(const float* __restrict__ W1, const float* __restrict__ b1,
                        float* __restrict__ out, int out_size) {
    int t = threadIdx.x; // 256 = D1
    float acc = (float)NN * b1[t];
    for (int f = 0; f < FIN; f++) acc += G_CS(f) * W1[(size_t)f * D1 + t];
    if (t < out_size) out[t] = acc * (1.f / 32.f);
    float pen = 0.f;
    if (t < 32) {
        float rs = 0.f;
        #pragma unroll
        for (int b = 0; b < 32; b++) rs += fabsf(G_ADJ(t * 32 + b));
        float d = G_ADJ(t * 33) / fmaxf(rs, 1e-12f);
        float contrib = (d - 1.f) * (d - 1.f) + 31.f * d * d;
        #pragma unroll
        for (int o = 16; o > 0; o >>= 1) contrib += __shfl_xor_sync(0xffffffffu, contrib, o);
        pen = contrib;
    }
    __syncthreads();
    for (int j = t; j < KC * KC + FIN; j += 256) g_small[j] = 0.f;
    if (t == 0 && out_size > D1) out[D1] = pen * (1.f / 1024.f);
}

// ---------------- launch ----------------
extern "C" void kernel_launch(void* const* d_in, const int* in_sizes, int n_in,
                              void* d_out, int out_size) {
    const float* feat  = (const float*)d_in[0];
    const int*   edges = (const int*)d_in[1];   // (2, E) int32
    const float* W1    = (const float*)d_in[2];
    const float* b1    = (const float*)d_in[3];
    const float* fc1W  = (const float*)d_in[4];
    const float* fc1b  = (const float*)d_in[5];
    const float* fc2W  = (const float*)d_in[6];
    const float* fc2b  = (const float*)d_in[7];
    float* out = (float*)d_out;

    k_degree<<<782, 256>>>(edges);                       // 1st
    k_scan2<<<2, 1024>>>();                              // 2nd
    k_fill<<<782, 256>>>(edges);                         // 3rd
    k_agg<<<(NN + 7) / 8, 256>>>(feat);                  // 4th  <- ncu capture target
    k_wcbc<<<FIN + 1, 128>>>(W1, fc1W, b1, fc1b);        // 5th
    k_gemm_fused<<<(NN + 63) / 64, 256>>>(fc2W, fc2b);   // 6th
    k_lapV<<<(NN * 32 + 255) / 256, 256>>>();            // 7th
    k_adj<<<148, 256>>>();                               // 8th (+ zero g_deg)
    k_final<<<1, 256>>>(W1, b1, out, out_size);          // 9th (+ zero g_small)
}